// round 14
// baseline (speedup 1.0000x reference)
#include <cuda_runtime.h>
#include <cuda_fp16.h>
#include <cstdint>

#define BATCH 16
#define HEADS 8
#define DH 32
#define LSP 1024
#define CIN 256
#define BH_N (BATCH*HEADS)
#define QT 64             // queries per CTA in attn (4 warps x 16)
#define KTL 128           // keys per tile
#define NKT (LSP/KTL)
#define KPAD 40           // K smem row stride (halves)
#define VPAD 136          // V smem row stride (halves)
#define XLT 256           // l-tile for qkv GEMM
#define XPAD 264          // Xs row stride (halves)
#define WPAD 40           // Ws row stride (halves)
#define VSTP 264          // V transpose-stage row stride (halves)

// fp16 staging: q,k as [bh][l][d]; v as [bh][d][l]
__device__ __half g_qh[(size_t)BH_N * LSP * DH];
__device__ __half g_kh[(size_t)BH_N * LSP * DH];
__device__ __half g_vh[(size_t)BH_N * DH * LSP];

// ---------------------------------------------------------------------------
// HMMA / LDSM / cp.async helpers
// ---------------------------------------------------------------------------
__device__ __forceinline__ void mma16816(
    float& d0, float& d1, float& d2, float& d3,
    uint32_t a0, uint32_t a1, uint32_t a2, uint32_t a3,
    uint32_t b0, uint32_t b1)
{
    asm volatile(
        "mma.sync.aligned.m16n8k16.row.col.f32.f16.f16.f32 "
        "{%0,%1,%2,%3}, {%4,%5,%6,%7}, {%8,%9}, {%0,%1,%2,%3};"
        : "+f"(d0), "+f"(d1), "+f"(d2), "+f"(d3)
        : "r"(a0), "r"(a1), "r"(a2), "r"(a3), "r"(b0), "r"(b1));
}

__device__ __forceinline__ void ldsm_x4(uint32_t& r0, uint32_t& r1,
                                        uint32_t& r2, uint32_t& r3,
                                        const void* p)
{
    uint32_t a = (uint32_t)__cvta_generic_to_shared(p);
    asm volatile(
        "ldmatrix.sync.aligned.m8n8.x4.shared.b16 {%0,%1,%2,%3}, [%4];"
        : "=r"(r0), "=r"(r1), "=r"(r2), "=r"(r3) : "r"(a));
}

__device__ __forceinline__ void ldsm_x4_trans(uint32_t& r0, uint32_t& r1,
                                              uint32_t& r2, uint32_t& r3,
                                              const void* p)
{
    uint32_t a = (uint32_t)__cvta_generic_to_shared(p);
    asm volatile(
        "ldmatrix.sync.aligned.m8n8.x4.trans.shared.b16 {%0,%1,%2,%3}, [%4];"
        : "=r"(r0), "=r"(r1), "=r"(r2), "=r"(r3) : "r"(a));
}

__device__ __forceinline__ void cp16(void* smem, const void* gmem)
{
    uint32_t a = (uint32_t)__cvta_generic_to_shared(smem);
    asm volatile("cp.async.cg.shared.global [%0], [%1], 16;"
                 :: "r"(a), "l"(gmem));
}

__device__ __forceinline__ uint32_t exp2_f16x2(float t0, float t1)
{
    uint32_t p;
    asm("cvt.rn.f16x2.f32 %0, %1, %2;" : "=r"(p) : "f"(t1), "f"(t0));
    asm("ex2.approx.f16x2 %0, %0;" : "+r"(p));
    return p;
}

// ---------------------------------------------------------------------------
// Kernel 1: grouped 1x1 conv as HMMA GEMM (unchanged from R12).
// ---------------------------------------------------------------------------
__global__ __launch_bounds__(256) void qkv_kernel(
    const float* __restrict__ x,
    const float* __restrict__ wq,
    const float* __restrict__ wk,
    const float* __restrict__ wv)
{
    __shared__ __half Xs[32][XPAD];      // [c][l]
    __shared__ __half Ws[3][32][WPAD];   // [mat][o][c]
    __shared__ __half Vst[32][VSTP];     // [d][l] transpose stage

    const int l0  = blockIdx.x * XLT;
    const int bh  = blockIdx.y;
    const int b   = bh >> 3;
    const int h   = bh & 7;
    const int tid = threadIdx.x;
    const int wid = tid >> 5;
    const int lane = tid & 31;
    const int gid = lane >> 2;
    const int tig = lane & 3;

    for (int idx = tid; idx < 32 * 64; idx += 256) {
        const int c  = idx >> 6;
        const int l4 = (idx & 63) * 4;
        const float4 v = *(const float4*)(x +
            ((size_t)(b * CIN + h * 32 + c) * LSP) + l0 + l4);
        __half2 h0 = __floats2half2_rn(v.x, v.y);
        __half2 h1 = __floats2half2_rn(v.z, v.w);
        *(__half2*)&Xs[c][l4]     = h0;
        *(__half2*)&Xs[c][l4 + 2] = h1;
    }
    {
        const float* wp[3] = {wq, wk, wv};
        for (int idx = tid; idx < 3072; idx += 256) {
            const int mat = idx >> 10;
            const int o   = (idx >> 5) & 31;
            const int c   = idx & 31;
            Ws[mat][o][c] = __float2half(wp[mat][(h * 32 + o) * 32 + c]);
        }
    }
    __syncthreads();

    const int krow = lane & 7;
    const int kcol = ((lane >> 3) & 3) * 8;
    const int arow_g = ((lane >> 4) << 3) + (lane & 7);
    const int acol_g = ((lane >> 3) & 1) * 8;

    float divs[4];
    #pragma unroll
    for (int nc = 0; nc < 4; nc++)
        divs[nc] = __expf(-0.03597789207803197f *
                          (float)(h * 32 + nc * 8 + tig * 2));

    const int m0 = wid * 32;

    #pragma unroll
    for (int mc = 0; mc < 2; mc++) {
        const int m = m0 + mc * 16;
        uint32_t a[2][4];
        #pragma unroll
        for (int ks = 0; ks < 2; ks++)
            ldsm_x4_trans(a[ks][0], a[ks][1], a[ks][2], a[ks][3],
                          &Xs[ks * 16 + arow_g][m + acol_g]);

        #pragma unroll
        for (int mat = 0; mat < 3; mat++) {
            #pragma unroll
            for (int nc = 0; nc < 4; nc++) {
                uint32_t b0, b1, b2, b3;
                ldsm_x4(b0, b1, b2, b3, &Ws[mat][nc * 8 + krow][kcol]);
                float d0 = 0.f, d1 = 0.f, d2 = 0.f, d3 = 0.f;
                mma16816(d0, d1, d2, d3,
                         a[0][0], a[0][1], a[0][2], a[0][3], b0, b1);
                mma16816(d0, d1, d2, d3,
                         a[1][0], a[1][1], a[1][2], a[1][3], b2, b3);

                const int lrow = l0 + m + gid;
                const int lml  = m + gid;
                const int dch  = nc * 8 + tig * 2;

                if (mat == 0) {
                    __half2 v0 = __floats2half2_rn(d0, d1);
                    __half2 v1 = __floats2half2_rn(d2, d3);
                    *(__half2*)(g_qh + ((size_t)bh * LSP + lrow)     * DH + dch) = v0;
                    *(__half2*)(g_qh + ((size_t)bh * LSP + lrow + 8) * DH + dch) = v1;
                } else if (mat == 1) {
                    float s0, c0, s1, c1;
                    __sincosf(divs[nc] * (float)lrow,       &s0, &c0);
                    __sincosf(divs[nc] * (float)(lrow + 8), &s1, &c1);
                    __half2 v0 = __floats2half2_rn(d0 + s0, d1 + c0);
                    __half2 v1 = __floats2half2_rn(d2 + s1, d3 + c1);
                    *(__half2*)(g_kh + ((size_t)bh * LSP + lrow)     * DH + dch) = v0;
                    *(__half2*)(g_kh + ((size_t)bh * LSP + lrow + 8) * DH + dch) = v1;
                } else {
                    Vst[dch    ][lml    ] = __float2half(d0);
                    Vst[dch + 1][lml    ] = __float2half(d1);
                    Vst[dch    ][lml + 8] = __float2half(d2);
                    Vst[dch + 1][lml + 8] = __float2half(d3);
                }
            }
        }
    }

    __syncthreads();
    {
        __half* vb = g_vh + (size_t)bh * DH * LSP + l0;
        #pragma unroll
        for (int i = tid; i < 1024; i += 256) {
            const int d = i >> 5;
            const int ch = (i & 31) * 8;
            *(uint4*)(vb + (size_t)d * LSP + ch) = *(const uint4*)&Vst[d][ch];
        }
    }
}

// ---------------------------------------------------------------------------
// Kernel 2: flash attention. 128-thread CTAs (QT=64) -> 4 independent sync
// domains per SM. Double-buffered cp.async, split softmax, lsum ones-MMA.
// ---------------------------------------------------------------------------
__global__ __launch_bounds__(128, 4) void attn_kernel(float* __restrict__ out)
{
    __shared__ __half Ks[2][KTL][KPAD];   // [buf][key][d]
    __shared__ __half Vs[2][DH][VPAD];    // [buf][d][key]

    const int tid  = threadIdx.x;
    const int wid  = tid >> 5;            // 0..3
    const int lane = tid & 31;
    const int gid  = lane >> 2;
    const int tig  = lane & 3;
    const int bh   = blockIdx.y;
    const int q0   = blockIdx.x * QT + wid * 16;
    const uint32_t ONE2 = 0x3C003C00u;
    const float L2E = 1.4426950408889634f;

    const __half* kbase = g_kh + (size_t)bh * LSP * DH;
    const __half* vbase = g_vh + (size_t)bh * DH * LSP;

    uint32_t qa[8];
    {
        const __half* qb = g_qh + ((size_t)bh * LSP + q0) * DH;
        #pragma unroll
        for (int kk = 0; kk < 2; kk++) {
            qa[kk*4+0] = *(const uint32_t*)(qb + (gid    ) * DH + kk*16     + tig*2);
            qa[kk*4+1] = *(const uint32_t*)(qb + (gid + 8) * DH + kk*16     + tig*2);
            qa[kk*4+2] = *(const uint32_t*)(qb + (gid    ) * DH + kk*16 + 8 + tig*2);
            qa[kk*4+3] = *(const uint32_t*)(qb + (gid + 8) * DH + kk*16 + 8 + tig*2);
        }
    }

    // staging: 128 threads. K: row=tid, 4x16B chunks. V: 4 chunks strided.
    // prefetch tile 0 into buffer 0
    {
        #pragma unroll
        for (int j = 0; j < 4; j++)
            cp16(&Ks[0][tid][j * 8], kbase + (size_t)tid * DH + j * 8);
        #pragma unroll
        for (int j = 0; j < 4; j++) {
            const int i = tid + 128 * j;
            const int r = i >> 4, c = (i & 15) * 8;
            cp16(&Vs[0][r][c], vbase + (size_t)r * LSP + c);
        }
        asm volatile("cp.async.commit_group;" ::: "memory");
    }

    float o[16];
    #pragma unroll
    for (int i = 0; i < 16; i++) o[i] = 0.f;
    float m0 = -1e30f, m1 = -1e30f, l0 = 0.f, l1 = 0.f;

    const int krow = lane & 7;
    const int kcol = ((lane >> 3) & 3) * 8;

    for (int kt = 0; kt < NKT; kt++) {
        const int buf = kt & 1;
        // prefetch next tile into the other buffer
        if (kt + 1 < NKT) {
            const size_t koff = (size_t)(kt + 1) * KTL;
            #pragma unroll
            for (int j = 0; j < 4; j++)
                cp16(&Ks[buf^1][tid][j * 8], kbase + (koff + tid) * DH + j * 8);
            #pragma unroll
            for (int j = 0; j < 4; j++) {
                const int i = tid + 128 * j;
                const int r = i >> 4, c = (i & 15) * 8;
                cp16(&Vs[buf^1][r][c], vbase + (size_t)r * LSP + koff + c);
            }
            asm volatile("cp.async.commit_group;" ::: "memory");
            asm volatile("cp.async.wait_group 1;" ::: "memory");
        } else {
            asm volatile("cp.async.wait_group 0;" ::: "memory");
        }
        __syncthreads();

        // ---- S = Q x K^T ----
        float s[16][4];
        #pragma unroll
        for (int j = 0; j < 16; j++) {
            uint32_t b0, b1, b2, b3;
            ldsm_x4(b0, b1, b2, b3, &Ks[buf][j * 8 + krow][kcol]);
            s[j][0] = s[j][1] = s[j][2] = s[j][3] = 0.f;
            mma16816(s[j][0], s[j][1], s[j][2], s[j][3],
                     qa[0], qa[1], qa[2], qa[3], b0, b1);
            mma16816(s[j][0], s[j][1], s[j][2], s[j][3],
                     qa[4], qa[5], qa[6], qa[7], b2, b3);
        }

        // ---- two independent 64-key online-softmax + PV steps ----
        #pragma unroll
        for (int half = 0; half < 2; half++) {
            const int jb = half * 8;
            float r0[4], r1[4];
            #pragma unroll
            for (int j = 0; j < 4; j++) {
                r0[j] = fmaxf(fmaxf(s[jb+2*j][0], s[jb+2*j][1]),
                              fmaxf(s[jb+2*j+1][0], s[jb+2*j+1][1]));
                r1[j] = fmaxf(fmaxf(s[jb+2*j][2], s[jb+2*j][3]),
                              fmaxf(s[jb+2*j+1][2], s[jb+2*j+1][3]));
            }
            r0[0] = fmaxf(fmaxf(r0[0], r0[1]), fmaxf(r0[2], r0[3]));
            r1[0] = fmaxf(fmaxf(r1[0], r1[1]), fmaxf(r1[2], r1[3]));
            float nm0 = fmaxf(m0, r0[0]);
            float nm1 = fmaxf(m1, r1[0]);
            nm0 = fmaxf(nm0, __shfl_xor_sync(0xffffffffu, nm0, 1));
            nm0 = fmaxf(nm0, __shfl_xor_sync(0xffffffffu, nm0, 2));
            nm1 = fmaxf(nm1, __shfl_xor_sync(0xffffffffu, nm1, 1));
            nm1 = fmaxf(nm1, __shfl_xor_sync(0xffffffffu, nm1, 2));
            const float c0 = __expf(m0 - nm0);
            const float c1 = __expf(m1 - nm1);
            m0 = nm0; m1 = nm1;
            l0 *= c0;  l1 *= c1;
            #pragma unroll
            for (int nc = 0; nc < 4; nc++) {
                o[nc*4+0] *= c0; o[nc*4+1] *= c0;
                o[nc*4+2] *= c1; o[nc*4+3] *= c1;
            }

            const float nb0 = -m0 * L2E;
            const float nb1 = -m1 * L2E;
            #pragma unroll
            for (int j = jb; j < jb + 8; j++) {
                float t00 = fmaf(s[j][0], L2E, nb0);
                float t01 = fmaf(s[j][1], L2E, nb0);
                float t10 = fmaf(s[j][2], L2E, nb1);
                float t11 = fmaf(s[j][3], L2E, nb1);
                s[j][0] = __uint_as_float(exp2_f16x2(t00, t01));
                s[j][1] = __uint_as_float(exp2_f16x2(t10, t11));
            }

            {
                float z0 = 0.f, z1 = 0.f, z2 = 0.f, z3 = 0.f;
                #pragma unroll
                for (int c = 0; c < 4; c++) {
                    mma16816(z0, z1, z2, z3,
                             __float_as_uint(s[jb + 2*c    ][0]),
                             __float_as_uint(s[jb + 2*c    ][1]),
                             __float_as_uint(s[jb + 2*c + 1][0]),
                             __float_as_uint(s[jb + 2*c + 1][1]),
                             ONE2, ONE2);
                }
                l0 += z0;
                l1 += z2;
            }

            #pragma unroll
            for (int nc = 0; nc < 4; nc++) {
                float& d0 = o[nc*4+0];
                float& d1 = o[nc*4+1];
                float& d2 = o[nc*4+2];
                float& d3 = o[nc*4+3];
                #pragma unroll
                for (int ci = 0; ci < 2; ci++) {
                    const int cc = half * 2 + ci;
                    uint32_t v0, v1, v2, v3;
                    ldsm_x4(v0, v1, v2, v3,
                            &Vs[buf][nc * 8 + krow][cc * 32 + kcol]);
                    const int c = jb + ci * 4;
                    mma16816(d0, d1, d2, d3,
                             __float_as_uint(s[c    ][0]),
                             __float_as_uint(s[c    ][1]),
                             __float_as_uint(s[c + 1][0]),
                             __float_as_uint(s[c + 1][1]),
                             v0, v1);
                    mma16816(d0, d1, d2, d3,
                             __float_as_uint(s[c + 2][0]),
                             __float_as_uint(s[c + 2][1]),
                             __float_as_uint(s[c + 3][0]),
                             __float_as_uint(s[c + 3][1]),
                             v2, v3);
                }
            }
        }
        __syncthreads();   // all warps done with this buffer before next prefetch overwrites
    }

    const float inv0 = 1.0f / l0;
    const float inv1 = 1.0f / l1;

    float* ob = out + (size_t)bh * DH * LSP;
    #pragma unroll
    for (int nc = 0; nc < 4; nc++) {
        const int d = nc * 8 + tig * 2;
        ob[(size_t)(d    ) * LSP + q0 + gid    ] = o[nc*4+0] * inv0;
        ob[(size_t)(d + 1) * LSP + q0 + gid    ] = o[nc*4+1] * inv0;
        ob[(size_t)(d    ) * LSP + q0 + gid + 8] = o[nc*4+2] * inv1;
        ob[(size_t)(d + 1) * LSP + q0 + gid + 8] = o[nc*4+3] * inv1;
    }
}

// ---------------------------------------------------------------------------
extern "C" void kernel_launch(void* const* d_in, const int* in_sizes, int n_in,
                              void* d_out, int out_size)
{
    const float* x  = (const float*)d_in[0];
    const float* wq = (const float*)d_in[1];
    const float* wk = (const float*)d_in[2];
    const float* wv = (const float*)d_in[3];
    float* out = (float*)d_out;

    dim3 g1(LSP / XLT, BH_N);
    qkv_kernel<<<g1, 256>>>(x, wq, wk, wv);

    dim3 g2(LSP / QT, BH_N);
    attn_kernel<<<g2, 128>>>(out);
}

// round 15
// speedup vs baseline: 1.1815x; 1.1815x over previous
#include <cuda_runtime.h>
#include <cuda_fp16.h>
#include <cstdint>

#define BATCH 16
#define HEADS 8
#define DH 32
#define LSP 1024
#define CIN 256
#define BH_N (BATCH*HEADS)
#define QT 128            // queries per CTA in attn (8 warps x 16)
#define KTL 128           // keys per tile
#define NKT (LSP/KTL)
#define KPAD 40           // K smem row stride (halves)
#define VPAD 136          // V smem row stride (halves)
#define XLT 256           // l-tile for qkv GEMM
#define XPAD 264          // Xs row stride (halves)
#define WPAD 40           // Ws row stride (halves)
#define VSTP 264          // V stage row stride (halves), rows=32
#define QSTP 40           // Q/K stage row stride (halves), rows=256

// fp16 staging: q,k as [bh][l][d]; v as [bh][d][l]
__device__ __half g_qh[(size_t)BH_N * LSP * DH];
__device__ __half g_kh[(size_t)BH_N * LSP * DH];
__device__ __half g_vh[(size_t)BH_N * DH * LSP];

// ---------------------------------------------------------------------------
// HMMA / LDSM / cp.async helpers
// ---------------------------------------------------------------------------
__device__ __forceinline__ void mma16816(
    float& d0, float& d1, float& d2, float& d3,
    uint32_t a0, uint32_t a1, uint32_t a2, uint32_t a3,
    uint32_t b0, uint32_t b1)
{
    asm volatile(
        "mma.sync.aligned.m16n8k16.row.col.f32.f16.f16.f32 "
        "{%0,%1,%2,%3}, {%4,%5,%6,%7}, {%8,%9}, {%0,%1,%2,%3};"
        : "+f"(d0), "+f"(d1), "+f"(d2), "+f"(d3)
        : "r"(a0), "r"(a1), "r"(a2), "r"(a3), "r"(b0), "r"(b1));
}

__device__ __forceinline__ void ldsm_x4(uint32_t& r0, uint32_t& r1,
                                        uint32_t& r2, uint32_t& r3,
                                        const void* p)
{
    uint32_t a = (uint32_t)__cvta_generic_to_shared(p);
    asm volatile(
        "ldmatrix.sync.aligned.m8n8.x4.shared.b16 {%0,%1,%2,%3}, [%4];"
        : "=r"(r0), "=r"(r1), "=r"(r2), "=r"(r3) : "r"(a));
}

__device__ __forceinline__ void ldsm_x4_trans(uint32_t& r0, uint32_t& r1,
                                              uint32_t& r2, uint32_t& r3,
                                              const void* p)
{
    uint32_t a = (uint32_t)__cvta_generic_to_shared(p);
    asm volatile(
        "ldmatrix.sync.aligned.m8n8.x4.trans.shared.b16 {%0,%1,%2,%3}, [%4];"
        : "=r"(r0), "=r"(r1), "=r"(r2), "=r"(r3) : "r"(a));
}

__device__ __forceinline__ void cp16(void* smem, const void* gmem)
{
    uint32_t a = (uint32_t)__cvta_generic_to_shared(smem);
    asm volatile("cp.async.cg.shared.global [%0], [%1], 16;"
                 :: "r"(a), "l"(gmem));
}

__device__ __forceinline__ uint32_t exp2_f16x2(float t0, float t1)
{
    uint32_t p;
    asm("cvt.rn.f16x2.f32 %0, %1, %2;" : "=r"(p) : "f"(t1), "f"(t0));
    asm("ex2.approx.f16x2 %0, %0;" : "+r"(p));
    return p;
}

__device__ __forceinline__ uint32_t packh2(float a, float b)
{
    __half2 h = __floats2half2_rn(a, b);
    return *(uint32_t*)&h;
}

// ---------------------------------------------------------------------------
// Kernel 1: grouped 1x1 conv as HMMA GEMM. ALL three outputs now flushed
// through a shared staging buffer with coalesced 16B global stores.
// ---------------------------------------------------------------------------
__global__ __launch_bounds__(256) void qkv_kernel(
    const float* __restrict__ x,
    const float* __restrict__ wq,
    const float* __restrict__ wk,
    const float* __restrict__ wv)
{
    __shared__ __half Xs[32][XPAD];          // [c][l]
    __shared__ __half Ws[3][32][WPAD];       // [mat][o][c]
    __shared__ __half Stage[256 * QSTP];     // union: V=[32][VSTP], Q/K=[256][QSTP]

    const int l0  = blockIdx.x * XLT;
    const int bh  = blockIdx.y;
    const int b   = bh >> 3;
    const int h   = bh & 7;
    const int tid = threadIdx.x;
    const int wid = tid >> 5;
    const int lane = tid & 31;
    const int gid = lane >> 2;
    const int tig = lane & 3;

    for (int idx = tid; idx < 32 * 64; idx += 256) {
        const int c  = idx >> 6;
        const int l4 = (idx & 63) * 4;
        const float4 v = *(const float4*)(x +
            ((size_t)(b * CIN + h * 32 + c) * LSP) + l0 + l4);
        __half2 h0 = __floats2half2_rn(v.x, v.y);
        __half2 h1 = __floats2half2_rn(v.z, v.w);
        *(__half2*)&Xs[c][l4]     = h0;
        *(__half2*)&Xs[c][l4 + 2] = h1;
    }
    {
        const float* wp[3] = {wq, wk, wv};
        for (int idx = tid; idx < 3072; idx += 256) {
            const int mat = idx >> 10;
            const int o   = (idx >> 5) & 31;
            const int c   = idx & 31;
            Ws[mat][o][c] = __float2half(wp[mat][(h * 32 + o) * 32 + c]);
        }
    }
    __syncthreads();

    const int krow = lane & 7;
    const int kcol = ((lane >> 3) & 3) * 8;
    const int arow_g = ((lane >> 4) << 3) + (lane & 7);
    const int acol_g = ((lane >> 3) & 1) * 8;

    float divs[4];
    #pragma unroll
    for (int nc = 0; nc < 4; nc++)
        divs[nc] = __expf(-0.03597789207803197f *
                          (float)(h * 32 + nc * 8 + tig * 2));

    const int m0 = wid * 32;
    uint32_t qf[16], kf[16];     // Q/K fragments kept in registers

    #pragma unroll
    for (int mc = 0; mc < 2; mc++) {
        const int m = m0 + mc * 16;
        uint32_t a[2][4];
        #pragma unroll
        for (int ks = 0; ks < 2; ks++)
            ldsm_x4_trans(a[ks][0], a[ks][1], a[ks][2], a[ks][3],
                          &Xs[ks * 16 + arow_g][m + acol_g]);

        #pragma unroll
        for (int mat = 0; mat < 3; mat++) {
            #pragma unroll
            for (int nc = 0; nc < 4; nc++) {
                uint32_t b0, b1, b2, b3;
                ldsm_x4(b0, b1, b2, b3, &Ws[mat][nc * 8 + krow][kcol]);
                float d0 = 0.f, d1 = 0.f, d2 = 0.f, d3 = 0.f;
                mma16816(d0, d1, d2, d3,
                         a[0][0], a[0][1], a[0][2], a[0][3], b0, b1);
                mma16816(d0, d1, d2, d3,
                         a[1][0], a[1][1], a[1][2], a[1][3], b2, b3);

                const int lrow = l0 + m + gid;      // global l
                const int lml  = m + gid;           // local l
                const int dch  = nc * 8 + tig * 2;
                const int fi   = mc * 8 + nc * 2;

                if (mat == 0) {
                    qf[fi]     = packh2(d0, d1);
                    qf[fi + 1] = packh2(d2, d3);
                } else if (mat == 1) {
                    float s0, c0, s1, c1;
                    __sincosf(divs[nc] * (float)lrow,       &s0, &c0);
                    __sincosf(divs[nc] * (float)(lrow + 8), &s1, &c1);
                    kf[fi]     = packh2(d0 + s0, d1 + c0);
                    kf[fi + 1] = packh2(d2 + s1, d3 + c1);
                } else {
                    Stage[(dch    ) * VSTP + lml    ] = __float2half(d0);
                    Stage[(dch + 1) * VSTP + lml    ] = __float2half(d1);
                    Stage[(dch    ) * VSTP + lml + 8] = __float2half(d2);
                    Stage[(dch + 1) * VSTP + lml + 8] = __float2half(d3);
                }
            }
        }
    }

    // ---- flush V ([d][l] stage -> strided coalesced rows) ----
    __syncthreads();
    {
        __half* vb = g_vh + (size_t)bh * DH * LSP + l0;
        #pragma unroll
        for (int i = tid; i < 1024; i += 256) {
            const int d = i >> 5;
            const int ch = (i & 31) * 8;
            *(uint4*)(vb + (size_t)d * LSP + ch) =
                *(const uint4*)&Stage[d * VSTP + ch];
        }
    }

    // ---- stage + flush Q, then K ([l][d] stage -> fully contiguous) ----
    #pragma unroll
    for (int mat = 0; mat < 2; mat++) {
        __syncthreads();
        const uint32_t* f = (mat == 0) ? qf : kf;
        #pragma unroll
        for (int mc = 0; mc < 2; mc++) {
            const int lml = m0 + mc * 16 + gid;
            #pragma unroll
            for (int nc = 0; nc < 4; nc++) {
                const int dch = nc * 8 + tig * 2;
                const int fi  = mc * 8 + nc * 2;
                *(uint32_t*)&Stage[(lml    ) * QSTP + dch] = f[fi];
                *(uint32_t*)&Stage[(lml + 8) * QSTP + dch] = f[fi + 1];
            }
        }
        __syncthreads();
        __half* dst = ((mat == 0) ? g_qh : g_kh) +
                      ((size_t)bh * LSP + l0) * DH;
        #pragma unroll
        for (int i = tid; i < 1024; i += 256) {
            const int l = i >> 2;
            const int c = (i & 3) * 8;
            *(uint4*)(dst + (size_t)l * DH + c) =
                *(const uint4*)&Stage[l * QSTP + c];
        }
    }
}

// ---------------------------------------------------------------------------
// Kernel 2: flash attention (R12 structure; prefetch issued BEFORE Q load).
// ---------------------------------------------------------------------------
__global__ __launch_bounds__(256, 2) void attn_kernel(float* __restrict__ out)
{
    __shared__ __half Ks[3][KTL][KPAD];   // [buf][key][d]
    __shared__ __half Vs[3][DH][VPAD];    // [buf][d][key]

    const int tid  = threadIdx.x;
    const int wid  = tid >> 5;
    const int lane = tid & 31;
    const int gid  = lane >> 2;
    const int tig  = lane & 3;
    const int bh   = blockIdx.y;
    const int q0   = blockIdx.x * QT + wid * 16;
    const uint32_t ONE2 = 0x3C003C00u;
    const float L2E = 1.4426950408889634f;

    const __half* kbase = g_kh + (size_t)bh * LSP * DH;
    const __half* vbase = g_vh + (size_t)bh * DH * LSP;

    const int kr = tid >> 1, kc = (tid & 1) * 16;
    const int vr0 = tid >> 4,         vc0 = (tid & 15) * 8;
    const int vr1 = (tid + 256) >> 4, vc1 = ((tid + 256) & 15) * 8;

    // prefetch tiles 0,1 FIRST (hide Q-load latency underneath)
    #pragma unroll
    for (int t = 0; t < 2; t++) {
        const size_t koff = (size_t)t * KTL;
        cp16(&Ks[t][kr][kc],     kbase + (koff + kr) * DH + kc);
        cp16(&Ks[t][kr][kc + 8], kbase + (koff + kr) * DH + kc + 8);
        cp16(&Vs[t][vr0][vc0],   vbase + (size_t)vr0 * LSP + koff + vc0);
        cp16(&Vs[t][vr1][vc1],   vbase + (size_t)vr1 * LSP + koff + vc1);
        asm volatile("cp.async.commit_group;" ::: "memory");
    }

    uint32_t qa[8];
    {
        const __half* qb = g_qh + ((size_t)bh * LSP + q0) * DH;
        #pragma unroll
        for (int kk = 0; kk < 2; kk++) {
            qa[kk*4+0] = *(const uint32_t*)(qb + (gid    ) * DH + kk*16     + tig*2);
            qa[kk*4+1] = *(const uint32_t*)(qb + (gid + 8) * DH + kk*16     + tig*2);
            qa[kk*4+2] = *(const uint32_t*)(qb + (gid    ) * DH + kk*16 + 8 + tig*2);
            qa[kk*4+3] = *(const uint32_t*)(qb + (gid + 8) * DH + kk*16 + 8 + tig*2);
        }
    }

    float o[16];
    #pragma unroll
    for (int i = 0; i < 16; i++) o[i] = 0.f;
    float m0 = -1e30f, m1 = -1e30f, l0 = 0.f, l1 = 0.f;

    const int krow = lane & 7;
    const int kcol = ((lane >> 3) & 3) * 8;

    for (int kt = 0; kt < NKT; kt++) {
        const int buf = kt % 3;
        if (kt + 1 < NKT) {
            asm volatile("cp.async.wait_group 1;" ::: "memory");
        } else {
            asm volatile("cp.async.wait_group 0;" ::: "memory");
        }
        __syncthreads();
        if (kt + 2 < NKT) {
            const int nb = (kt + 2) % 3;
            const size_t koff = (size_t)(kt + 2) * KTL;
            cp16(&Ks[nb][kr][kc],     kbase + (koff + kr) * DH + kc);
            cp16(&Ks[nb][kr][kc + 8], kbase + (koff + kr) * DH + kc + 8);
            cp16(&Vs[nb][vr0][vc0],   vbase + (size_t)vr0 * LSP + koff + vc0);
            cp16(&Vs[nb][vr1][vc1],   vbase + (size_t)vr1 * LSP + koff + vc1);
            asm volatile("cp.async.commit_group;" ::: "memory");
        }

        // ---- S = Q x K^T ----
        float s[16][4];
        #pragma unroll
        for (int j = 0; j < 16; j++) {
            uint32_t b0, b1, b2, b3;
            ldsm_x4(b0, b1, b2, b3, &Ks[buf][j * 8 + krow][kcol]);
            s[j][0] = s[j][1] = s[j][2] = s[j][3] = 0.f;
            mma16816(s[j][0], s[j][1], s[j][2], s[j][3],
                     qa[0], qa[1], qa[2], qa[3], b0, b1);
            mma16816(s[j][0], s[j][1], s[j][2], s[j][3],
                     qa[4], qa[5], qa[6], qa[7], b2, b3);
        }

        // ---- two independent 64-key online-softmax + PV steps ----
        #pragma unroll
        for (int half = 0; half < 2; half++) {
            const int jb = half * 8;
            float r0[4], r1[4];
            #pragma unroll
            for (int j = 0; j < 4; j++) {
                r0[j] = fmaxf(fmaxf(s[jb+2*j][0], s[jb+2*j][1]),
                              fmaxf(s[jb+2*j+1][0], s[jb+2*j+1][1]));
                r1[j] = fmaxf(fmaxf(s[jb+2*j][2], s[jb+2*j][3]),
                              fmaxf(s[jb+2*j+1][2], s[jb+2*j+1][3]));
            }
            r0[0] = fmaxf(fmaxf(r0[0], r0[1]), fmaxf(r0[2], r0[3]));
            r1[0] = fmaxf(fmaxf(r1[0], r1[1]), fmaxf(r1[2], r1[3]));
            float nm0 = fmaxf(m0, r0[0]);
            float nm1 = fmaxf(m1, r1[0]);
            nm0 = fmaxf(nm0, __shfl_xor_sync(0xffffffffu, nm0, 1));
            nm0 = fmaxf(nm0, __shfl_xor_sync(0xffffffffu, nm0, 2));
            nm1 = fmaxf(nm1, __shfl_xor_sync(0xffffffffu, nm1, 1));
            nm1 = fmaxf(nm1, __shfl_xor_sync(0xffffffffu, nm1, 2));
            const float c0 = __expf(m0 - nm0);
            const float c1 = __expf(m1 - nm1);
            m0 = nm0; m1 = nm1;
            l0 *= c0;  l1 *= c1;
            #pragma unroll
            for (int nc = 0; nc < 4; nc++) {
                o[nc*4+0] *= c0; o[nc*4+1] *= c0;
                o[nc*4+2] *= c1; o[nc*4+3] *= c1;
            }

            const float nb0 = -m0 * L2E;
            const float nb1 = -m1 * L2E;
            #pragma unroll
            for (int j = jb; j < jb + 8; j++) {
                float t00 = fmaf(s[j][0], L2E, nb0);
                float t01 = fmaf(s[j][1], L2E, nb0);
                float t10 = fmaf(s[j][2], L2E, nb1);
                float t11 = fmaf(s[j][3], L2E, nb1);
                s[j][0] = __uint_as_float(exp2_f16x2(t00, t01));
                s[j][1] = __uint_as_float(exp2_f16x2(t10, t11));
            }

            {
                float z0 = 0.f, z1 = 0.f, z2 = 0.f, z3 = 0.f;
                #pragma unroll
                for (int c = 0; c < 4; c++) {
                    mma16816(z0, z1, z2, z3,
                             __float_as_uint(s[jb + 2*c    ][0]),
                             __float_as_uint(s[jb + 2*c    ][1]),
                             __float_as_uint(s[jb + 2*c + 1][0]),
                             __float_as_uint(s[jb + 2*c + 1][1]),
                             ONE2, ONE2);
                }
                l0 += z0;
                l1 += z2;
            }

            #pragma unroll
            for (int nc = 0; nc < 4; nc++) {
                float& d0 = o[nc*4+0];
                float& d1 = o[nc*4+1];
                float& d2 = o[nc*4+2];
                float& d3 = o[nc*4+3];
                #pragma unroll
                for (int ci = 0; ci < 2; ci++) {
                    const int cc = half * 2 + ci;
                    uint32_t v0, v1, v2, v3;
                    ldsm_x4(v0, v1, v2, v3,
                            &Vs[buf][nc * 8 + krow][cc * 32 + kcol]);
                    const int c = jb + ci * 4;
                    mma16816(d0, d1, d2, d3,
                             __float_as_uint(s[c    ][0]),
                             __float_as_uint(s[c    ][1]),
                             __float_as_uint(s[c + 1][0]),
                             __float_as_uint(s[c + 1][1]),
                             v0, v1);
                    mma16816(d0, d1, d2, d3,
                             __float_as_uint(s[c + 2][0]),
                             __float_as_uint(s[c + 2][1]),
                             __float_as_uint(s[c + 3][0]),
                             __float_as_uint(s[c + 3][1]),
                             v2, v3);
                }
            }
        }
    }

    const float inv0 = 1.0f / l0;
    const float inv1 = 1.0f / l1;

    float* ob = out + (size_t)bh * DH * LSP;
    #pragma unroll
    for (int nc = 0; nc < 4; nc++) {
        const int d = nc * 8 + tig * 2;
        ob[(size_t)(d    ) * LSP + q0 + gid    ] = o[nc*4+0] * inv0;
        ob[(size_t)(d + 1) * LSP + q0 + gid    ] = o[nc*4+1] * inv0;
        ob[(size_t)(d    ) * LSP + q0 + gid + 8] = o[nc*4+2] * inv1;
        ob[(size_t)(d + 1) * LSP + q0 + gid + 8] = o[nc*4+3] * inv1;
    }
}

// ---------------------------------------------------------------------------
extern "C" void kernel_launch(void* const* d_in, const int* in_sizes, int n_in,
                              void* d_out, int out_size)
{
    const float* x  = (const float*)d_in[0];
    const float* wq = (const float*)d_in[1];
    const float* wk = (const float*)d_in[2];
    const float* wv = (const float*)d_in[3];
    float* out = (float*)d_out;

    dim3 g1(LSP / XLT, BH_N);
    qkv_kernel<<<g1, 256>>>(x, wq, wk, wv);

    dim3 g2(LSP / QT, BH_N);
    attn_kernel<<<g2, 256>>>(out);
}

// round 16
// speedup vs baseline: 1.1901x; 1.0072x over previous
#include <cuda_runtime.h>
#include <cuda_fp16.h>
#include <cstdint>

#define BATCH 16
#define HEADS 8
#define DH 32
#define LSP 1024
#define CIN 256
#define BH_N (BATCH*HEADS)
#define QT 128            // queries per CTA in attn (8 warps x 16)
#define KTL 128           // keys per tile
#define NKT (LSP/KTL)
#define NPAIR (NKT/2)
#define KPAD 40           // K smem row stride (halves)
#define VPAD 136          // V smem row stride (halves)
#define XLT 256           // l-tile for qkv GEMM
#define XPAD 264          // Xs row stride (halves)
#define WPAD 40           // Ws row stride (halves)
#define VSTP 264          // V transpose-stage row stride (halves)

// fp16 staging: q,k as [bh][l][d]; v as [bh][d][l]
__device__ __half g_qh[(size_t)BH_N * LSP * DH];
__device__ __half g_kh[(size_t)BH_N * LSP * DH];
__device__ __half g_vh[(size_t)BH_N * DH * LSP];

// ---------------------------------------------------------------------------
// HMMA / LDSM / cp.async helpers
// ---------------------------------------------------------------------------
__device__ __forceinline__ void mma16816(
    float& d0, float& d1, float& d2, float& d3,
    uint32_t a0, uint32_t a1, uint32_t a2, uint32_t a3,
    uint32_t b0, uint32_t b1)
{
    asm volatile(
        "mma.sync.aligned.m16n8k16.row.col.f32.f16.f16.f32 "
        "{%0,%1,%2,%3}, {%4,%5,%6,%7}, {%8,%9}, {%0,%1,%2,%3};"
        : "+f"(d0), "+f"(d1), "+f"(d2), "+f"(d3)
        : "r"(a0), "r"(a1), "r"(a2), "r"(a3), "r"(b0), "r"(b1));
}

__device__ __forceinline__ void ldsm_x4(uint32_t& r0, uint32_t& r1,
                                        uint32_t& r2, uint32_t& r3,
                                        const void* p)
{
    uint32_t a = (uint32_t)__cvta_generic_to_shared(p);
    asm volatile(
        "ldmatrix.sync.aligned.m8n8.x4.shared.b16 {%0,%1,%2,%3}, [%4];"
        : "=r"(r0), "=r"(r1), "=r"(r2), "=r"(r3) : "r"(a));
}

__device__ __forceinline__ void ldsm_x4_trans(uint32_t& r0, uint32_t& r1,
                                              uint32_t& r2, uint32_t& r3,
                                              const void* p)
{
    uint32_t a = (uint32_t)__cvta_generic_to_shared(p);
    asm volatile(
        "ldmatrix.sync.aligned.m8n8.x4.trans.shared.b16 {%0,%1,%2,%3}, [%4];"
        : "=r"(r0), "=r"(r1), "=r"(r2), "=r"(r3) : "r"(a));
}

__device__ __forceinline__ void cp16(void* smem, const void* gmem)
{
    uint32_t a = (uint32_t)__cvta_generic_to_shared(smem);
    asm volatile("cp.async.cg.shared.global [%0], [%1], 16;"
                 :: "r"(a), "l"(gmem));
}

__device__ __forceinline__ uint32_t exp2_f16x2(float t0, float t1)
{
    uint32_t p;
    asm("cvt.rn.f16x2.f32 %0, %1, %2;" : "=r"(p) : "f"(t1), "f"(t0));
    asm("ex2.approx.f16x2 %0, %0;" : "+r"(p));
    return p;
}

// ---------------------------------------------------------------------------
// Kernel 1: grouped 1x1 conv as HMMA GEMM (R12 version — proven 14.1us).
// ---------------------------------------------------------------------------
__global__ __launch_bounds__(256) void qkv_kernel(
    const float* __restrict__ x,
    const float* __restrict__ wq,
    const float* __restrict__ wk,
    const float* __restrict__ wv)
{
    __shared__ __half Xs[32][XPAD];      // [c][l]
    __shared__ __half Ws[3][32][WPAD];   // [mat][o][c]
    __shared__ __half Vst[32][VSTP];     // [d][l] transpose stage

    const int l0  = blockIdx.x * XLT;
    const int bh  = blockIdx.y;
    const int b   = bh >> 3;
    const int h   = bh & 7;
    const int tid = threadIdx.x;
    const int wid = tid >> 5;
    const int lane = tid & 31;
    const int gid = lane >> 2;
    const int tig = lane & 3;

    for (int idx = tid; idx < 32 * 64; idx += 256) {
        const int c  = idx >> 6;
        const int l4 = (idx & 63) * 4;
        const float4 v = *(const float4*)(x +
            ((size_t)(b * CIN + h * 32 + c) * LSP) + l0 + l4);
        __half2 h0 = __floats2half2_rn(v.x, v.y);
        __half2 h1 = __floats2half2_rn(v.z, v.w);
        *(__half2*)&Xs[c][l4]     = h0;
        *(__half2*)&Xs[c][l4 + 2] = h1;
    }
    {
        const float* wp[3] = {wq, wk, wv};
        for (int idx = tid; idx < 3072; idx += 256) {
            const int mat = idx >> 10;
            const int o   = (idx >> 5) & 31;
            const int c   = idx & 31;
            Ws[mat][o][c] = __float2half(wp[mat][(h * 32 + o) * 32 + c]);
        }
    }
    __syncthreads();

    const int krow = lane & 7;
    const int kcol = ((lane >> 3) & 3) * 8;
    const int arow_g = ((lane >> 4) << 3) + (lane & 7);
    const int acol_g = ((lane >> 3) & 1) * 8;

    float divs[4];
    #pragma unroll
    for (int nc = 0; nc < 4; nc++)
        divs[nc] = __expf(-0.03597789207803197f *
                          (float)(h * 32 + nc * 8 + tig * 2));

    const int m0 = wid * 32;

    #pragma unroll
    for (int mc = 0; mc < 2; mc++) {
        const int m = m0 + mc * 16;
        uint32_t a[2][4];
        #pragma unroll
        for (int ks = 0; ks < 2; ks++)
            ldsm_x4_trans(a[ks][0], a[ks][1], a[ks][2], a[ks][3],
                          &Xs[ks * 16 + arow_g][m + acol_g]);

        #pragma unroll
        for (int mat = 0; mat < 3; mat++) {
            #pragma unroll
            for (int nc = 0; nc < 4; nc++) {
                uint32_t b0, b1, b2, b3;
                ldsm_x4(b0, b1, b2, b3, &Ws[mat][nc * 8 + krow][kcol]);
                float d0 = 0.f, d1 = 0.f, d2 = 0.f, d3 = 0.f;
                mma16816(d0, d1, d2, d3,
                         a[0][0], a[0][1], a[0][2], a[0][3], b0, b1);
                mma16816(d0, d1, d2, d3,
                         a[1][0], a[1][1], a[1][2], a[1][3], b2, b3);

                const int lrow = l0 + m + gid;
                const int lml  = m + gid;
                const int dch  = nc * 8 + tig * 2;

                if (mat == 0) {
                    __half2 v0 = __floats2half2_rn(d0, d1);
                    __half2 v1 = __floats2half2_rn(d2, d3);
                    *(__half2*)(g_qh + ((size_t)bh * LSP + lrow)     * DH + dch) = v0;
                    *(__half2*)(g_qh + ((size_t)bh * LSP + lrow + 8) * DH + dch) = v1;
                } else if (mat == 1) {
                    float s0, c0, s1, c1;
                    __sincosf(divs[nc] * (float)lrow,       &s0, &c0);
                    __sincosf(divs[nc] * (float)(lrow + 8), &s1, &c1);
                    __half2 v0 = __floats2half2_rn(d0 + s0, d1 + c0);
                    __half2 v1 = __floats2half2_rn(d2 + s1, d3 + c1);
                    *(__half2*)(g_kh + ((size_t)bh * LSP + lrow)     * DH + dch) = v0;
                    *(__half2*)(g_kh + ((size_t)bh * LSP + lrow + 8) * DH + dch) = v1;
                } else {
                    Vst[dch    ][lml    ] = __float2half(d0);
                    Vst[dch + 1][lml    ] = __float2half(d1);
                    Vst[dch    ][lml + 8] = __float2half(d2);
                    Vst[dch + 1][lml + 8] = __float2half(d3);
                }
            }
        }
    }

    __syncthreads();
    {
        __half* vb = g_vh + (size_t)bh * DH * LSP + l0;
        #pragma unroll
        for (int i = tid; i < 1024; i += 256) {
            const int d = i >> 5;
            const int ch = (i & 31) * 8;
            *(uint4*)(vb + (size_t)d * LSP + ch) = *(const uint4*)&Vst[d][ch];
        }
    }
}

// ---------------------------------------------------------------------------
// Kernel 2: flash attention. 4 smem buffers, TWO tiles (256 keys) per
// __syncthreads — halves barrier count, doubles the warp-drift window so
// softmax (MUFU/ALU) of one warp overlaps MMA bursts of others.
// ---------------------------------------------------------------------------
__global__ __launch_bounds__(256, 2) void attn_kernel(float* __restrict__ out)
{
    __shared__ __half Ks[4][KTL][KPAD];   // [buf][key][d]
    __shared__ __half Vs[4][DH][VPAD];    // [buf][d][key]

    const int tid  = threadIdx.x;
    const int wid  = tid >> 5;
    const int lane = tid & 31;
    const int gid  = lane >> 2;
    const int tig  = lane & 3;
    const int bh   = blockIdx.y;
    const int q0   = blockIdx.x * QT + wid * 16;
    const uint32_t ONE2 = 0x3C003C00u;
    const float L2E = 1.4426950408889634f;

    const __half* kbase = g_kh + (size_t)bh * LSP * DH;
    const __half* vbase = g_vh + (size_t)bh * DH * LSP;

    const int kr = tid >> 1, kc = (tid & 1) * 16;
    const int vr0 = tid >> 4,         vc0 = (tid & 15) * 8;
    const int vr1 = (tid + 256) >> 4, vc1 = ((tid + 256) & 15) * 8;

    // prologue: prefetch pairs 0 (tiles 0,1 -> bufs 0,1) and 1 (tiles 2,3 -> bufs 2,3)
    #pragma unroll
    for (int t = 0; t < 4; t++) {
        const size_t koff = (size_t)t * KTL;
        cp16(&Ks[t][kr][kc],     kbase + (koff + kr) * DH + kc);
        cp16(&Ks[t][kr][kc + 8], kbase + (koff + kr) * DH + kc + 8);
        cp16(&Vs[t][vr0][vc0],   vbase + (size_t)vr0 * LSP + koff + vc0);
        cp16(&Vs[t][vr1][vc1],   vbase + (size_t)vr1 * LSP + koff + vc1);
        if (t & 1)
            asm volatile("cp.async.commit_group;" ::: "memory");
    }

    uint32_t qa[8];
    {
        const __half* qb = g_qh + ((size_t)bh * LSP + q0) * DH;
        #pragma unroll
        for (int kk = 0; kk < 2; kk++) {
            qa[kk*4+0] = *(const uint32_t*)(qb + (gid    ) * DH + kk*16     + tig*2);
            qa[kk*4+1] = *(const uint32_t*)(qb + (gid + 8) * DH + kk*16     + tig*2);
            qa[kk*4+2] = *(const uint32_t*)(qb + (gid    ) * DH + kk*16 + 8 + tig*2);
            qa[kk*4+3] = *(const uint32_t*)(qb + (gid + 8) * DH + kk*16 + 8 + tig*2);
        }
    }

    float o[16];
    #pragma unroll
    for (int i = 0; i < 16; i++) o[i] = 0.f;
    float m0 = -1e30f, m1 = -1e30f, l0 = 0.f, l1 = 0.f;

    const int krow = lane & 7;
    const int kcol = ((lane >> 3) & 3) * 8;

    for (int p = 0; p < NPAIR; p++) {
        // wait for pair p (at p==0, pair 1's group may stay pending)
        if (p == 0) {
            asm volatile("cp.async.wait_group 1;" ::: "memory");
        } else {
            asm volatile("cp.async.wait_group 0;" ::: "memory");
        }
        __syncthreads();
        // prefetch pair p+1 into bufs of pair p-1 (freed by the sync above)
        if (p >= 1 && p + 1 < NPAIR) {
            #pragma unroll
            for (int ti = 0; ti < 2; ti++) {
                const int t  = 2 * (p + 1) + ti;
                const int nb = t & 3;
                const size_t koff = (size_t)t * KTL;
                cp16(&Ks[nb][kr][kc],     kbase + (koff + kr) * DH + kc);
                cp16(&Ks[nb][kr][kc + 8], kbase + (koff + kr) * DH + kc + 8);
                cp16(&Vs[nb][vr0][vc0],   vbase + (size_t)vr0 * LSP + koff + vc0);
                cp16(&Vs[nb][vr1][vc1],   vbase + (size_t)vr1 * LSP + koff + vc1);
            }
            asm volatile("cp.async.commit_group;" ::: "memory");
        }

        // ---- process the two tiles of this pair (no barrier between) ----
        #pragma unroll
        for (int ti = 0; ti < 2; ti++) {
            const int buf = (2 * p + ti) & 3;

            // S = Q x K^T
            float s[16][4];
            #pragma unroll
            for (int j = 0; j < 16; j++) {
                uint32_t b0, b1, b2, b3;
                ldsm_x4(b0, b1, b2, b3, &Ks[buf][j * 8 + krow][kcol]);
                s[j][0] = s[j][1] = s[j][2] = s[j][3] = 0.f;
                mma16816(s[j][0], s[j][1], s[j][2], s[j][3],
                         qa[0], qa[1], qa[2], qa[3], b0, b1);
                mma16816(s[j][0], s[j][1], s[j][2], s[j][3],
                         qa[4], qa[5], qa[6], qa[7], b2, b3);
            }

            // two independent 64-key online-softmax + PV steps
            #pragma unroll
            for (int half = 0; half < 2; half++) {
                const int jb = half * 8;
                float r0[4], r1[4];
                #pragma unroll
                for (int j = 0; j < 4; j++) {
                    r0[j] = fmaxf(fmaxf(s[jb+2*j][0], s[jb+2*j][1]),
                                  fmaxf(s[jb+2*j+1][0], s[jb+2*j+1][1]));
                    r1[j] = fmaxf(fmaxf(s[jb+2*j][2], s[jb+2*j][3]),
                                  fmaxf(s[jb+2*j+1][2], s[jb+2*j+1][3]));
                }
                r0[0] = fmaxf(fmaxf(r0[0], r0[1]), fmaxf(r0[2], r0[3]));
                r1[0] = fmaxf(fmaxf(r1[0], r1[1]), fmaxf(r1[2], r1[3]));
                float nm0 = fmaxf(m0, r0[0]);
                float nm1 = fmaxf(m1, r1[0]);
                nm0 = fmaxf(nm0, __shfl_xor_sync(0xffffffffu, nm0, 1));
                nm0 = fmaxf(nm0, __shfl_xor_sync(0xffffffffu, nm0, 2));
                nm1 = fmaxf(nm1, __shfl_xor_sync(0xffffffffu, nm1, 1));
                nm1 = fmaxf(nm1, __shfl_xor_sync(0xffffffffu, nm1, 2));
                const float c0 = __expf(m0 - nm0);
                const float c1 = __expf(m1 - nm1);
                m0 = nm0; m1 = nm1;
                l0 *= c0;  l1 *= c1;
                #pragma unroll
                for (int nc = 0; nc < 4; nc++) {
                    o[nc*4+0] *= c0; o[nc*4+1] *= c0;
                    o[nc*4+2] *= c1; o[nc*4+3] *= c1;
                }

                const float nb0 = -m0 * L2E;
                const float nb1 = -m1 * L2E;
                #pragma unroll
                for (int j = jb; j < jb + 8; j++) {
                    float t00 = fmaf(s[j][0], L2E, nb0);
                    float t01 = fmaf(s[j][1], L2E, nb0);
                    float t10 = fmaf(s[j][2], L2E, nb1);
                    float t11 = fmaf(s[j][3], L2E, nb1);
                    s[j][0] = __uint_as_float(exp2_f16x2(t00, t01));
                    s[j][1] = __uint_as_float(exp2_f16x2(t10, t11));
                }

                {
                    float z0 = 0.f, z1 = 0.f, z2 = 0.f, z3 = 0.f;
                    #pragma unroll
                    for (int c = 0; c < 4; c++) {
                        mma16816(z0, z1, z2, z3,
                                 __float_as_uint(s[jb + 2*c    ][0]),
                                 __float_as_uint(s[jb + 2*c    ][1]),
                                 __float_as_uint(s[jb + 2*c + 1][0]),
                                 __float_as_uint(s[jb + 2*c + 1][1]),
                                 ONE2, ONE2);
                    }
                    l0 += z0;
                    l1 += z2;
                }

                #pragma unroll
                for (int nc = 0; nc < 4; nc++) {
                    float& d0 = o[nc*4+0];
                    float& d1 = o[nc*4+1];
                    float& d2 = o[nc*4+2];
                    float& d3 = o[nc*4+3];
                    #pragma unroll
                    for (int ci = 0; ci < 2; ci++) {
                        const int cc = half * 2 + ci;
                        uint32_t v0, v1, v2, v3;
                        ldsm_x4(v0, v1, v2, v3,
                                &Vs[buf][nc * 8 + krow][cc * 32 + kcol]);
                        const int c = jb + ci * 4;
                        mma16816(d0, d1, d2, d3,
                                 __float_as_uint(s[c    ][0]),
                                 __float_as_uint(s[c    ][1]),
                                 __float_as_uint(s[c + 1][0]),
                                 __float_as_uint(s[c + 1][1]),
                                 v0, v1);
                        mma16816(d0, d1, d2, d3,
                                 __float_as_uint(s[c + 2][0]),
                                 __float_as_uint(s[c + 2][1]),
                                 __float_as_uint(s[c + 3][0]),
                                 __float_as_uint(s[c + 3][1]),
                                 v2, v3);
                    }
                }
            }
        }
    }

    const float inv0 = 1.0f / l0;
    const float inv1 = 1.0f / l1;

    float* ob = out + (size_t)bh * DH * LSP;
    #pragma unroll
    for (int nc = 0; nc < 4; nc++) {
        const int d = nc * 8 + tig * 2;
        ob[(size_t)(d    ) * LSP + q0 + gid    ] = o[nc*4+0] * inv0;
        ob[(size_t)(d + 1) * LSP + q0 + gid    ] = o[nc*4+1] * inv0;
        ob[(size_t)(d    ) * LSP + q0 + gid + 8] = o[nc*4+2] * inv1;
        ob[(size_t)(d + 1) * LSP + q0 + gid + 8] = o[nc*4+3] * inv1;
    }
}

// ---------------------------------------------------------------------------
extern "C" void kernel_launch(void* const* d_in, const int* in_sizes, int n_in,
                              void* d_out, int out_size)
{
    const float* x  = (const float*)d_in[0];
    const float* wq = (const float*)d_in[1];
    const float* wk = (const float*)d_in[2];
    const float* wv = (const float*)d_in[3];
    float* out = (float*)d_out;

    dim3 g1(LSP / XLT, BH_N);
    qkv_kernel<<<g1, 256>>>(x, wq, wk, wv);

    dim3 g2(LSP / QT, BH_N);
    attn_kernel<<<g2, 256>>>(out);
}

// round 17
// speedup vs baseline: 1.2280x; 1.0319x over previous
#include <cuda_runtime.h>
#include <cuda_fp16.h>
#include <cstdint>

#define BATCH 16
#define HEADS 8
#define DH 32
#define LSP 1024
#define CIN 256
#define BH_N (BATCH*HEADS)
#define QT 128            // queries per CTA in attn (8 warps x 16)
#define KTL 128           // keys per tile
#define NKT (LSP/KTL)
#define KPAD 40           // K smem row stride (halves)
#define VPAD 136          // V smem row stride (halves)
#define XLT 256           // l-tile for qkv GEMM
#define XPAD 264          // Xs row stride (halves)
#define WPAD 40           // Ws row stride (halves)
#define VSTP 264          // V transpose-stage row stride (halves)

// fp16 staging: q,k as [bh][l][d]; v as [bh][d][l]
__device__ __half g_qh[(size_t)BH_N * LSP * DH];
__device__ __half g_kh[(size_t)BH_N * LSP * DH];
__device__ __half g_vh[(size_t)BH_N * DH * LSP];

// ---------------------------------------------------------------------------
// HMMA / LDSM / cp.async helpers
// ---------------------------------------------------------------------------
__device__ __forceinline__ void mma16816(
    float& d0, float& d1, float& d2, float& d3,
    uint32_t a0, uint32_t a1, uint32_t a2, uint32_t a3,
    uint32_t b0, uint32_t b1)
{
    asm volatile(
        "mma.sync.aligned.m16n8k16.row.col.f32.f16.f16.f32 "
        "{%0,%1,%2,%3}, {%4,%5,%6,%7}, {%8,%9}, {%0,%1,%2,%3};"
        : "+f"(d0), "+f"(d1), "+f"(d2), "+f"(d3)
        : "r"(a0), "r"(a1), "r"(a2), "r"(a3), "r"(b0), "r"(b1));
}

__device__ __forceinline__ void ldsm_x4(uint32_t& r0, uint32_t& r1,
                                        uint32_t& r2, uint32_t& r3,
                                        const void* p)
{
    uint32_t a = (uint32_t)__cvta_generic_to_shared(p);
    asm volatile(
        "ldmatrix.sync.aligned.m8n8.x4.shared.b16 {%0,%1,%2,%3}, [%4];"
        : "=r"(r0), "=r"(r1), "=r"(r2), "=r"(r3) : "r"(a));
}

__device__ __forceinline__ void ldsm_x4_trans(uint32_t& r0, uint32_t& r1,
                                              uint32_t& r2, uint32_t& r3,
                                              const void* p)
{
    uint32_t a = (uint32_t)__cvta_generic_to_shared(p);
    asm volatile(
        "ldmatrix.sync.aligned.m8n8.x4.trans.shared.b16 {%0,%1,%2,%3}, [%4];"
        : "=r"(r0), "=r"(r1), "=r"(r2), "=r"(r3) : "r"(a));
}

__device__ __forceinline__ void cp16(void* smem, const void* gmem)
{
    uint32_t a = (uint32_t)__cvta_generic_to_shared(smem);
    asm volatile("cp.async.cg.shared.global [%0], [%1], 16;"
                 :: "r"(a), "l"(gmem));
}

__device__ __forceinline__ uint32_t exp2_f16x2(float t0, float t1)
{
    uint32_t p;
    asm("cvt.rn.f16x2.f32 %0, %1, %2;" : "=r"(p) : "f"(t1), "f"(t0));
    asm("ex2.approx.f16x2 %0, %0;" : "+r"(p));
    return p;
}

// ---------------------------------------------------------------------------
// Kernel 1: grouped 1x1 conv as HMMA GEMM (R12 version — proven 14.1us).
// ---------------------------------------------------------------------------
__global__ __launch_bounds__(256) void qkv_kernel(
    const float* __restrict__ x,
    const float* __restrict__ wq,
    const float* __restrict__ wk,
    const float* __restrict__ wv)
{
    __shared__ __half Xs[32][XPAD];      // [c][l]
    __shared__ __half Ws[3][32][WPAD];   // [mat][o][c]
    __shared__ __half Vst[32][VSTP];     // [d][l] transpose stage

    const int l0  = blockIdx.x * XLT;
    const int bh  = blockIdx.y;
    const int b   = bh >> 3;
    const int h   = bh & 7;
    const int tid = threadIdx.x;
    const int wid = tid >> 5;
    const int lane = tid & 31;
    const int gid = lane >> 2;
    const int tig = lane & 3;

    for (int idx = tid; idx < 32 * 64; idx += 256) {
        const int c  = idx >> 6;
        const int l4 = (idx & 63) * 4;
        const float4 v = *(const float4*)(x +
            ((size_t)(b * CIN + h * 32 + c) * LSP) + l0 + l4);
        __half2 h0 = __floats2half2_rn(v.x, v.y);
        __half2 h1 = __floats2half2_rn(v.z, v.w);
        *(__half2*)&Xs[c][l4]     = h0;
        *(__half2*)&Xs[c][l4 + 2] = h1;
    }
    {
        const float* wp[3] = {wq, wk, wv};
        for (int idx = tid; idx < 3072; idx += 256) {
            const int mat = idx >> 10;
            const int o   = (idx >> 5) & 31;
            const int c   = idx & 31;
            Ws[mat][o][c] = __float2half(wp[mat][(h * 32 + o) * 32 + c]);
        }
    }
    __syncthreads();

    const int krow = lane & 7;
    const int kcol = ((lane >> 3) & 3) * 8;
    const int arow_g = ((lane >> 4) << 3) + (lane & 7);
    const int acol_g = ((lane >> 3) & 1) * 8;

    float divs[4];
    #pragma unroll
    for (int nc = 0; nc < 4; nc++)
        divs[nc] = __expf(-0.03597789207803197f *
                          (float)(h * 32 + nc * 8 + tig * 2));

    const int m0 = wid * 32;

    #pragma unroll
    for (int mc = 0; mc < 2; mc++) {
        const int m = m0 + mc * 16;
        uint32_t a[2][4];
        #pragma unroll
        for (int ks = 0; ks < 2; ks++)
            ldsm_x4_trans(a[ks][0], a[ks][1], a[ks][2], a[ks][3],
                          &Xs[ks * 16 + arow_g][m + acol_g]);

        #pragma unroll
        for (int mat = 0; mat < 3; mat++) {
            #pragma unroll
            for (int nc = 0; nc < 4; nc++) {
                uint32_t b0, b1, b2, b3;
                ldsm_x4(b0, b1, b2, b3, &Ws[mat][nc * 8 + krow][kcol]);
                float d0 = 0.f, d1 = 0.f, d2 = 0.f, d3 = 0.f;
                mma16816(d0, d1, d2, d3,
                         a[0][0], a[0][1], a[0][2], a[0][3], b0, b1);
                mma16816(d0, d1, d2, d3,
                         a[1][0], a[1][1], a[1][2], a[1][3], b2, b3);

                const int lrow = l0 + m + gid;
                const int lml  = m + gid;
                const int dch  = nc * 8 + tig * 2;

                if (mat == 0) {
                    __half2 v0 = __floats2half2_rn(d0, d1);
                    __half2 v1 = __floats2half2_rn(d2, d3);
                    *(__half2*)(g_qh + ((size_t)bh * LSP + lrow)     * DH + dch) = v0;
                    *(__half2*)(g_qh + ((size_t)bh * LSP + lrow + 8) * DH + dch) = v1;
                } else if (mat == 1) {
                    float s0, c0, s1, c1;
                    __sincosf(divs[nc] * (float)lrow,       &s0, &c0);
                    __sincosf(divs[nc] * (float)(lrow + 8), &s1, &c1);
                    __half2 v0 = __floats2half2_rn(d0 + s0, d1 + c0);
                    __half2 v1 = __floats2half2_rn(d2 + s1, d3 + c1);
                    *(__half2*)(g_kh + ((size_t)bh * LSP + lrow)     * DH + dch) = v0;
                    *(__half2*)(g_kh + ((size_t)bh * LSP + lrow + 8) * DH + dch) = v1;
                } else {
                    Vst[dch    ][lml    ] = __float2half(d0);
                    Vst[dch + 1][lml    ] = __float2half(d1);
                    Vst[dch    ][lml + 8] = __float2half(d2);
                    Vst[dch + 1][lml + 8] = __float2half(d3);
                }
            }
        }
    }

    __syncthreads();
    {
        __half* vb = g_vh + (size_t)bh * DH * LSP + l0;
        #pragma unroll
        for (int i = tid; i < 1024; i += 256) {
            const int d = i >> 5;
            const int ch = (i & 31) * 8;
            *(uint4*)(vb + (size_t)d * LSP + ch) = *(const uint4*)&Vst[d][ch];
        }
    }
}

// ---------------------------------------------------------------------------
// Kernel 2: flash attention (R15 structure — triple buffer, prefetch before
// Q load, split softmax, lsum ones-MMA moved AFTER PV in each half).
// ---------------------------------------------------------------------------
__global__ __launch_bounds__(256, 2) void attn_kernel(float* __restrict__ out)
{
    __shared__ __half Ks[3][KTL][KPAD];   // [buf][key][d]
    __shared__ __half Vs[3][DH][VPAD];    // [buf][d][key]

    const int tid  = threadIdx.x;
    const int wid  = tid >> 5;
    const int lane = tid & 31;
    const int gid  = lane >> 2;
    const int tig  = lane & 3;
    const int bh   = blockIdx.y;
    const int q0   = blockIdx.x * QT + wid * 16;
    const uint32_t ONE2 = 0x3C003C00u;
    const float L2E = 1.4426950408889634f;

    const __half* kbase = g_kh + (size_t)bh * LSP * DH;
    const __half* vbase = g_vh + (size_t)bh * DH * LSP;

    const int kr = tid >> 1, kc = (tid & 1) * 16;
    const int vr0 = tid >> 4,         vc0 = (tid & 15) * 8;
    const int vr1 = (tid + 256) >> 4, vc1 = ((tid + 256) & 15) * 8;

    // prefetch tiles 0,1 FIRST (hide Q-load latency underneath)
    #pragma unroll
    for (int t = 0; t < 2; t++) {
        const size_t koff = (size_t)t * KTL;
        cp16(&Ks[t][kr][kc],     kbase + (koff + kr) * DH + kc);
        cp16(&Ks[t][kr][kc + 8], kbase + (koff + kr) * DH + kc + 8);
        cp16(&Vs[t][vr0][vc0],   vbase + (size_t)vr0 * LSP + koff + vc0);
        cp16(&Vs[t][vr1][vc1],   vbase + (size_t)vr1 * LSP + koff + vc1);
        asm volatile("cp.async.commit_group;" ::: "memory");
    }

    uint32_t qa[8];
    {
        const __half* qb = g_qh + ((size_t)bh * LSP + q0) * DH;
        #pragma unroll
        for (int kk = 0; kk < 2; kk++) {
            qa[kk*4+0] = *(const uint32_t*)(qb + (gid    ) * DH + kk*16     + tig*2);
            qa[kk*4+1] = *(const uint32_t*)(qb + (gid + 8) * DH + kk*16     + tig*2);
            qa[kk*4+2] = *(const uint32_t*)(qb + (gid    ) * DH + kk*16 + 8 + tig*2);
            qa[kk*4+3] = *(const uint32_t*)(qb + (gid + 8) * DH + kk*16 + 8 + tig*2);
        }
    }

    float o[16];
    #pragma unroll
    for (int i = 0; i < 16; i++) o[i] = 0.f;
    float m0 = -1e30f, m1 = -1e30f, l0 = 0.f, l1 = 0.f;

    const int krow = lane & 7;
    const int kcol = ((lane >> 3) & 3) * 8;

    for (int kt = 0; kt < NKT; kt++) {
        const int buf = kt % 3;
        if (kt + 1 < NKT) {
            asm volatile("cp.async.wait_group 1;" ::: "memory");
        } else {
            asm volatile("cp.async.wait_group 0;" ::: "memory");
        }
        __syncthreads();
        if (kt + 2 < NKT) {
            const int nb = (kt + 2) % 3;
            const size_t koff = (size_t)(kt + 2) * KTL;
            cp16(&Ks[nb][kr][kc],     kbase + (koff + kr) * DH + kc);
            cp16(&Ks[nb][kr][kc + 8], kbase + (koff + kr) * DH + kc + 8);
            cp16(&Vs[nb][vr0][vc0],   vbase + (size_t)vr0 * LSP + koff + vc0);
            cp16(&Vs[nb][vr1][vc1],   vbase + (size_t)vr1 * LSP + koff + vc1);
            asm volatile("cp.async.commit_group;" ::: "memory");
        }

        // ---- S = Q x K^T ----
        float s[16][4];
        #pragma unroll
        for (int j = 0; j < 16; j++) {
            uint32_t b0, b1, b2, b3;
            ldsm_x4(b0, b1, b2, b3, &Ks[buf][j * 8 + krow][kcol]);
            s[j][0] = s[j][1] = s[j][2] = s[j][3] = 0.f;
            mma16816(s[j][0], s[j][1], s[j][2], s[j][3],
                     qa[0], qa[1], qa[2], qa[3], b0, b1);
            mma16816(s[j][0], s[j][1], s[j][2], s[j][3],
                     qa[4], qa[5], qa[6], qa[7], b2, b3);
        }

        // ---- two independent 64-key online-softmax + PV steps ----
        #pragma unroll
        for (int half = 0; half < 2; half++) {
            const int jb = half * 8;
            float r0[4], r1[4];
            #pragma unroll
            for (int j = 0; j < 4; j++) {
                r0[j] = fmaxf(fmaxf(s[jb+2*j][0], s[jb+2*j][1]),
                              fmaxf(s[jb+2*j+1][0], s[jb+2*j+1][1]));
                r1[j] = fmaxf(fmaxf(s[jb+2*j][2], s[jb+2*j][3]),
                              fmaxf(s[jb+2*j+1][2], s[jb+2*j+1][3]));
            }
            r0[0] = fmaxf(fmaxf(r0[0], r0[1]), fmaxf(r0[2], r0[3]));
            r1[0] = fmaxf(fmaxf(r1[0], r1[1]), fmaxf(r1[2], r1[3]));
            float nm0 = fmaxf(m0, r0[0]);
            float nm1 = fmaxf(m1, r1[0]);
            nm0 = fmaxf(nm0, __shfl_xor_sync(0xffffffffu, nm0, 1));
            nm0 = fmaxf(nm0, __shfl_xor_sync(0xffffffffu, nm0, 2));
            nm1 = fmaxf(nm1, __shfl_xor_sync(0xffffffffu, nm1, 1));
            nm1 = fmaxf(nm1, __shfl_xor_sync(0xffffffffu, nm1, 2));
            const float c0 = __expf(m0 - nm0);
            const float c1 = __expf(m1 - nm1);
            m0 = nm0; m1 = nm1;
            l0 *= c0;  l1 *= c1;
            #pragma unroll
            for (int nc = 0; nc < 4; nc++) {
                o[nc*4+0] *= c0; o[nc*4+1] *= c0;
                o[nc*4+2] *= c1; o[nc*4+3] *= c1;
            }

            const float nb0 = -m0 * L2E;
            const float nb1 = -m1 * L2E;
            #pragma unroll
            for (int j = jb; j < jb + 8; j++) {
                float t00 = fmaf(s[j][0], L2E, nb0);
                float t01 = fmaf(s[j][1], L2E, nb0);
                float t10 = fmaf(s[j][2], L2E, nb1);
                float t11 = fmaf(s[j][3], L2E, nb1);
                s[j][0] = __uint_as_float(exp2_f16x2(t00, t01));
                s[j][1] = __uint_as_float(exp2_f16x2(t10, t11));
            }

            // PV first (o-critical path), then the lsum ones-MMA fills in
            #pragma unroll
            for (int nc = 0; nc < 4; nc++) {
                float& d0 = o[nc*4+0];
                float& d1 = o[nc*4+1];
                float& d2 = o[nc*4+2];
                float& d3 = o[nc*4+3];
                #pragma unroll
                for (int ci = 0; ci < 2; ci++) {
                    const int cc = half * 2 + ci;
                    uint32_t v0, v1, v2, v3;
                    ldsm_x4(v0, v1, v2, v3,
                            &Vs[buf][nc * 8 + krow][cc * 32 + kcol]);
                    const int c = jb + ci * 4;
                    mma16816(d0, d1, d2, d3,
                             __float_as_uint(s[c    ][0]),
                             __float_as_uint(s[c    ][1]),
                             __float_as_uint(s[c + 1][0]),
                             __float_as_uint(s[c + 1][1]),
                             v0, v1);
                    mma16816(d0, d1, d2, d3,
                             __float_as_uint(s[c + 2][0]),
                             __float_as_uint(s[c + 2][1]),
                             __float_as_uint(s[c + 3][0]),
                             __float_as_uint(s[c + 3][1]),
                             v2, v3);
                }
            }

            // lsum = P x ones (result needed only at the very end)
            {
                float z0 = 0.f, z1 = 0.f, z2 = 0.f, z3 = 0.f;
                #pragma unroll
                for (int c = 0; c < 4; c++) {
                    mma16816(z0, z1, z2, z3,
                             __float_as_uint(s[jb + 2*c    ][0]),
                             __float_as_uint(s[jb + 2*c    ][1]),
                             __float_as_uint(s[jb + 2*c + 1][0]),
                             __float_as_uint(s[jb + 2*c + 1][1]),
                             ONE2, ONE2);
                }
                l0 += z0;
                l1 += z2;
            }
        }
    }

    const float inv0 = 1.0f / l0;
    const float inv1 = 1.0f / l1;

    float* ob = out + (size_t)bh * DH * LSP;
    #pragma unroll
    for (int nc = 0; nc < 4; nc++) {
        const int d = nc * 8 + tig * 2;
        ob[(size_t)(d    ) * LSP + q0 + gid    ] = o[nc*4+0] * inv0;
        ob[(size_t)(d + 1) * LSP + q0 + gid    ] = o[nc*4+1] * inv0;
        ob[(size_t)(d    ) * LSP + q0 + gid + 8] = o[nc*4+2] * inv1;
        ob[(size_t)(d + 1) * LSP + q0 + gid + 8] = o[nc*4+3] * inv1;
    }
}

// ---------------------------------------------------------------------------
extern "C" void kernel_launch(void* const* d_in, const int* in_sizes, int n_in,
                              void* d_out, int out_size)
{
    const float* x  = (const float*)d_in[0];
    const float* wq = (const float*)d_in[1];
    const float* wk = (const float*)d_in[2];
    const float* wv = (const float*)d_in[3];
    float* out = (float*)d_out;

    dim3 g1(LSP / XLT, BH_N);
    qkv_kernel<<<g1, 256>>>(x, wq, wk, wv);

    dim3 g2(LSP / QT, BH_N);
    attn_kernel<<<g2, 256>>>(out);
}